// round 8
// baseline (speedup 1.0000x reference)
#include <cuda_runtime.h>
#include <cuda_bf16.h>

#define N_TRIALS   8
#define T_TOTAL    600
#define N_NEURONS  30000
#define T_USE      500
#define N_SAMPLES  50
#define MAX_COUNT  200
#define N_BINS     16
#define EPS        1e-7f
#define SYNC_COST  10.0f

#define NJ          8                 // per-sample id chunks (dynamic split of [0,cnt))
#define JMAX        32                // >= ceil(MAX_COUNT/NJ) = 25

__constant__ int c_bins[N_BINS] = {1,1,2,3,4,6,9,13,18,26,38,55,78,113,162,234};

// Scratch (device globals: allocation is forbidden)
__device__ float        g_part[NJ * N_SAMPLES * T_USE];  // partial gather sums
__device__ float        g_fano[N_BINS * N_SAMPLES];      // per-(bin,sample) fano
__device__ unsigned int g_scnt[N_SAMPLES];               // per-sample completion counters
__device__ unsigned int g_ticket;                        // sample-finisher ticket
// all counters are reset in-kernel by their finishers -> graph-replay safe

// ---------------------------------------------------------------------------
// Fused kernel. Block = (sample, j-chunk), 128 threads.
//  A) gather: each thread owns 4 timesteps (t, t+128, t+256, t+384), streams
//     this chunk's ids 2 at a time -> 8 independent scattered LDGs in flight.
//  B) the block that completes its sample (per-sample atomic counter hits NJ)
//     combines the 8 partials into smem and computes all 16 bins' fanos
//     (4 warps x 4 bins) -- overlapped with other samples' gathers.
//  C) the last sample-finisher (global ticket) reduces g_fano -> scalar loss.
// mask is prefix-form (arange < count) => effective count = sum(mask);
// ids[0:cnt] are exactly the active ids (duplicates preserved).
// sample_ids arrives as int32 (JAX x64-disabled demotes int64 -> int32).
// ---------------------------------------------------------------------------
__global__ void __launch_bounds__(128)
fused_kernel(const float* __restrict__ spikes,
             const int*   __restrict__ trials,
             const int*   __restrict__ ids,
             const float* __restrict__ mask,
             const float* __restrict__ exp_fanos,
             float*       __restrict__ out)
{
    __shared__ int   s_ids[JMAX];
    __shared__ int   s_cnt;
    __shared__ float s_row[T_USE];
    __shared__ bool  s_sample_done, s_all_done;

    const int s   = blockIdx.x;
    const int jc  = blockIdx.y;
    const int tid = threadIdx.x;
    const int lane = tid & 31;
    const int wid  = tid >> 5;

    // ---- effective count + this chunk's ids ----
    if (tid == 0) s_cnt = 0;
    __syncthreads();
    int local = 0;
    #pragma unroll
    for (int j = tid; j < MAX_COUNT; j += 128)
        if (mask[s * MAX_COUNT + j] != 0.0f) local++;
    if (local) atomicAdd(&s_cnt, local);
    __syncthreads();

    const int cnt = s_cnt;
    const int lo  = (jc * cnt) / NJ;
    const int m   = ((jc + 1) * cnt) / NJ - lo;    // <= 25
    if (tid < m)
        s_ids[tid] = ids[s * MAX_COUNT + lo + tid];
    __syncthreads();

    // ---- A) gather: 4 t-streams per thread ----
    const size_t trialOff = (size_t)trials[s] * ((size_t)T_TOTAL * N_NEURONS);
    const int t0 = tid, t1 = tid + 128, t2 = tid + 256, t3 = tid + 384;
    const bool v3 = (t3 < T_USE);
    const int t3c = v3 ? t3 : 0;

    const float* __restrict__ b0 = spikes + trialOff + (size_t)t0  * N_NEURONS;
    const float* __restrict__ b1 = spikes + trialOff + (size_t)t1  * N_NEURONS;
    const float* __restrict__ b2 = spikes + trialOff + (size_t)t2  * N_NEURONS;
    const float* __restrict__ b3 = spikes + trialOff + (size_t)t3c * N_NEURONS;

    float a0 = 0.0f, a1 = 0.0f, a2 = 0.0f, a3 = 0.0f;
    int j = 0;
    for (; j + 2 <= m; j += 2) {
        const int idA = s_ids[j];
        const int idB = s_ids[j + 1];
        float x0 = __ldg(b0 + idA), x1 = __ldg(b1 + idA);
        float x2 = __ldg(b2 + idA), x3 = __ldg(b3 + idA);
        float y0 = __ldg(b0 + idB), y1 = __ldg(b1 + idB);
        float y2 = __ldg(b2 + idB), y3 = __ldg(b3 + idB);
        a0 += x0 + y0;  a1 += x1 + y1;
        a2 += x2 + y2;  a3 += x3 + y3;
    }
    if (j < m) {
        const int idA = s_ids[j];
        a0 += __ldg(b0 + idA);  a1 += __ldg(b1 + idA);
        a2 += __ldg(b2 + idA);  a3 += __ldg(b3 + idA);
    }

    float* __restrict__ dst = g_part + (jc * N_SAMPLES + s) * T_USE;
    dst[t0] = a0;
    dst[t1] = a1;
    dst[t2] = a2;
    if (v3) dst[t3] = a3;

    // ---- B) sample-completion handoff ----
    __threadfence();
    __syncthreads();
    if (tid == 0) {
        unsigned int old = atomicAdd(&g_scnt[s], 1u);
        s_sample_done = (old == NJ - 1);
        if (s_sample_done) g_scnt[s] = 0;     // reset for next graph replay
    }
    __syncthreads();
    if (!s_sample_done) return;

    // this block is the last of its sample: combine partials -> smem row
    for (int i = tid; i < T_USE; i += 128) {
        float v = 0.0f;
        #pragma unroll
        for (int c = 0; c < NJ; ++c)
            v += g_part[(c * N_SAMPLES + s) * T_USE + i];
        s_row[i] = v;
    }
    __syncthreads();

    // 4 warps x 4 bins: single-pass sum / sum-of-squares per bin
    #pragma unroll
    for (int rep = 0; rep < 4; ++rep) {
        const int b  = wid + rep * 4;
        const int bs = c_bins[b];
        const int nb = T_USE / bs;

        float sum = 0.0f, sumsq = 0.0f;
        for (int k = lane; k < nb; k += 32) {
            const float* rk = s_row + k * bs;
            float c = 0.0f;
            int u = 0;
            for (; u + 4 <= bs; u += 4) {
                float q0 = rk[u], q1 = rk[u+1], q2 = rk[u+2], q3 = rk[u+3];
                c += (q0 + q1) + (q2 + q3);
            }
            for (; u < bs; ++u) c += rk[u];
            sum   += c;
            sumsq += c * c;
        }
        #pragma unroll
        for (int off = 16; off > 0; off >>= 1) {
            sum   += __shfl_down_sync(0xffffffff, sum,   off);
            sumsq += __shfl_down_sync(0xffffffff, sumsq, off);
        }
        if (lane == 0) {
            const float mean = sum / (float)nb;
            const float var  = sumsq / (float)nb - mean * mean;
            g_fano[b * N_SAMPLES + s] = var / fmaxf(mean, EPS);
        }
    }

    // ---- C) last sample-finisher reduces g_fano -> scalar loss ----
    __threadfence();
    __syncthreads();
    if (tid == 0) {
        unsigned int old = atomicAdd(&g_ticket, 1u);
        s_all_done = (old == N_SAMPLES - 1);
        if (s_all_done) g_ticket = 0;         // reset for next graph replay
    }
    __syncthreads();

    if (s_all_done && wid == 0) {
        float d2 = 0.0f;
        if (lane < N_BINS) {
            float fsum = 0.0f;
            for (int q = 0; q < N_SAMPLES; ++q)
                fsum += g_fano[lane * N_SAMPLES + q];
            const float fm = fsum / (float)N_SAMPLES;
            const float d  = exp_fanos[lane] - fm;
            d2 = d * d;
        }
        #pragma unroll
        for (int off = 16; off > 0; off >>= 1)
            d2 += __shfl_down_sync(0xffffffff, d2, off);
        if (lane == 0)
            out[0] = SYNC_COST * (d2 / (float)N_BINS);
    }
}

// ---------------------------------------------------------------------------
// Inputs (metadata order):
//   0: spikes float32 [8,600,30000]   1: experimental_fanos_mean float32 [16]
//   2: sample_trials int32 [50]       3: sample_ids int32 [50,200]
//   4: sample_mask float32 [50,200]   out: float32 scalar
// ---------------------------------------------------------------------------
extern "C" void kernel_launch(void* const* d_in, const int* in_sizes, int n_in,
                              void* d_out, int out_size)
{
    const float* spikes = (const float*)d_in[0];
    const float* expf_  = (const float*)d_in[1];
    const int*   trials = (const int*)d_in[2];
    const int*   ids    = (const int*)d_in[3];
    const float* mask   = (const float*)d_in[4];
    float*       out    = (float*)d_out;

    dim3 grid(N_SAMPLES, NJ);
    fused_kernel<<<grid, 128>>>(spikes, trials, ids, mask, expf_, out);
}

// round 9
// speedup vs baseline: 1.0139x; 1.0139x over previous
#include <cuda_runtime.h>
#include <cuda_bf16.h>

#define N_TRIALS   8
#define T_TOTAL    600
#define N_NEURONS  30000
#define T_USE      500
#define N_SAMPLES  50
#define MAX_COUNT  200
#define N_BINS     16
#define EPS        1e-7f
#define SYNC_COST  10.0f

#define NJ          8                 // per-sample id chunks (dynamic split of [0,cnt))
#define TS          4                 // t-slices (128 timesteps each)
#define JMAX        32                // >= ceil(MAX_COUNT/NJ) = 25
#define BLOCKS_PER_SAMPLE (NJ * TS)   // 32

__constant__ int c_bins[N_BINS] = {1,1,2,3,4,6,9,13,18,26,38,55,78,113,162,234};

// Scratch (device globals: allocation is forbidden)
__device__ float        g_part[NJ * N_SAMPLES * T_USE];  // partial gather sums
__device__ float        g_fano[N_BINS * N_SAMPLES];      // per-(bin,sample) fano
__device__ unsigned int g_scnt[N_SAMPLES];               // per-sample completion counters
__device__ unsigned int g_ticket;                        // sample-finisher ticket
// all counters are reset in-kernel by their finishers -> graph-replay safe

// ---------------------------------------------------------------------------
// Fused kernel. Block = (sample, j-chunk, t-slice), 128 threads; 1600 blocks
// => 43 warps/SM so enough outstanding DRAM misses to saturate bandwidth
// (R8 profile: DRAM 49% @ only 10.8 warps/SM; traffic is ~197MB of 128B
// lines with no reuse, so the only lever left is bandwidth utilization).
//  A) gather: thread owns one timestep t = ts*128+tid; 8-wide id unroll.
//  B) block that completes its sample (counter hits 32) combines the 8
//     partials into smem and computes all 16 bins' fanos (4 warps x 4 bins),
//     overlapped with other samples' gathers.
//  C) last sample-finisher (ticket) reduces g_fano -> scalar loss.
// mask is prefix-form (arange < count) => effective count = sum(mask);
// ids[0:cnt] are exactly the active ids (duplicates preserved).
// sample_ids arrives as int32 (JAX x64-disabled demotes int64 -> int32).
// ---------------------------------------------------------------------------
__global__ void __launch_bounds__(128)
fused_kernel(const float* __restrict__ spikes,
             const int*   __restrict__ trials,
             const int*   __restrict__ ids,
             const float* __restrict__ mask,
             const float* __restrict__ exp_fanos,
             float*       __restrict__ out)
{
    __shared__ int   s_ids[JMAX];
    __shared__ int   s_cnt;
    __shared__ float s_row[T_USE];
    __shared__ bool  s_sample_done, s_all_done;

    const int s    = blockIdx.x;
    const int jc   = blockIdx.y;
    const int ts   = blockIdx.z;
    const int tid  = threadIdx.x;
    const int lane = tid & 31;
    const int wid  = tid >> 5;

    // ---- effective count + this chunk's ids ----
    if (tid == 0) s_cnt = 0;
    __syncthreads();
    int local = 0;
    #pragma unroll
    for (int j = tid; j < MAX_COUNT; j += 128)
        if (mask[s * MAX_COUNT + j] != 0.0f) local++;
    if (local) atomicAdd(&s_cnt, local);
    __syncthreads();

    const int cnt = s_cnt;
    const int lo  = (jc * cnt) / NJ;
    const int m   = ((jc + 1) * cnt) / NJ - lo;    // <= 25
    if (tid < m)
        s_ids[tid] = ids[s * MAX_COUNT + lo + tid];
    __syncthreads();

    // ---- A) gather: one timestep per thread ----
    const int t = ts * 128 + tid;
    if (t < T_USE) {
        const float* __restrict__ base =
            spikes + (size_t)trials[s] * ((size_t)T_TOTAL * N_NEURONS)
                   + (size_t)t * N_NEURONS;
        float acc = 0.0f;
        int j = 0;
        for (; j + 8 <= m; j += 8) {
            float v0 = __ldg(base + s_ids[j + 0]);
            float v1 = __ldg(base + s_ids[j + 1]);
            float v2 = __ldg(base + s_ids[j + 2]);
            float v3 = __ldg(base + s_ids[j + 3]);
            float v4 = __ldg(base + s_ids[j + 4]);
            float v5 = __ldg(base + s_ids[j + 5]);
            float v6 = __ldg(base + s_ids[j + 6]);
            float v7 = __ldg(base + s_ids[j + 7]);
            acc += ((v0 + v1) + (v2 + v3)) + ((v4 + v5) + (v6 + v7));
        }
        for (; j < m; ++j) acc += __ldg(base + s_ids[j]);
        g_part[(jc * N_SAMPLES + s) * T_USE + t] = acc;
    }

    // ---- B) sample-completion handoff ----
    __threadfence();
    __syncthreads();
    if (tid == 0) {
        unsigned int old = atomicAdd(&g_scnt[s], 1u);
        s_sample_done = (old == BLOCKS_PER_SAMPLE - 1);
        if (s_sample_done) g_scnt[s] = 0;     // reset for next graph replay
    }
    __syncthreads();
    if (!s_sample_done) return;

    // this block is the last of its sample: combine partials -> smem row
    for (int i = tid; i < T_USE; i += 128) {
        float v = 0.0f;
        #pragma unroll
        for (int c = 0; c < NJ; ++c)
            v += g_part[(c * N_SAMPLES + s) * T_USE + i];
        s_row[i] = v;
    }
    __syncthreads();

    // 4 warps x 4 bins: single-pass sum / sum-of-squares per bin
    #pragma unroll
    for (int rep = 0; rep < 4; ++rep) {
        const int b  = wid + rep * 4;
        const int bs = c_bins[b];
        const int nb = T_USE / bs;

        float sum = 0.0f, sumsq = 0.0f;
        for (int k = lane; k < nb; k += 32) {
            const float* rk = s_row + k * bs;
            float c = 0.0f;
            int u = 0;
            for (; u + 4 <= bs; u += 4) {
                float q0 = rk[u], q1 = rk[u+1], q2 = rk[u+2], q3 = rk[u+3];
                c += (q0 + q1) + (q2 + q3);
            }
            for (; u < bs; ++u) c += rk[u];
            sum   += c;
            sumsq += c * c;
        }
        #pragma unroll
        for (int off = 16; off > 0; off >>= 1) {
            sum   += __shfl_down_sync(0xffffffff, sum,   off);
            sumsq += __shfl_down_sync(0xffffffff, sumsq, off);
        }
        if (lane == 0) {
            const float mean = sum / (float)nb;
            const float var  = sumsq / (float)nb - mean * mean;
            g_fano[b * N_SAMPLES + s] = var / fmaxf(mean, EPS);
        }
    }

    // ---- C) last sample-finisher reduces g_fano -> scalar loss ----
    __threadfence();
    __syncthreads();
    if (tid == 0) {
        unsigned int old = atomicAdd(&g_ticket, 1u);
        s_all_done = (old == N_SAMPLES - 1);
        if (s_all_done) g_ticket = 0;         // reset for next graph replay
    }
    __syncthreads();

    if (s_all_done && wid == 0) {
        float d2 = 0.0f;
        if (lane < N_BINS) {
            float fsum = 0.0f;
            for (int q = 0; q < N_SAMPLES; ++q)
                fsum += g_fano[lane * N_SAMPLES + q];
            const float fm = fsum / (float)N_SAMPLES;
            const float d  = exp_fanos[lane] - fm;
            d2 = d * d;
        }
        #pragma unroll
        for (int off = 16; off > 0; off >>= 1)
            d2 += __shfl_down_sync(0xffffffff, d2, off);
        if (lane == 0)
            out[0] = SYNC_COST * (d2 / (float)N_BINS);
    }
}

// ---------------------------------------------------------------------------
// Inputs (metadata order):
//   0: spikes float32 [8,600,30000]   1: experimental_fanos_mean float32 [16]
//   2: sample_trials int32 [50]       3: sample_ids int32 [50,200]
//   4: sample_mask float32 [50,200]   out: float32 scalar
// ---------------------------------------------------------------------------
extern "C" void kernel_launch(void* const* d_in, const int* in_sizes, int n_in,
                              void* d_out, int out_size)
{
    const float* spikes = (const float*)d_in[0];
    const float* expf_  = (const float*)d_in[1];
    const int*   trials = (const int*)d_in[2];
    const int*   ids    = (const int*)d_in[3];
    const float* mask   = (const float*)d_in[4];
    float*       out    = (float*)d_out;

    dim3 grid(N_SAMPLES, NJ, TS);
    fused_kernel<<<grid, 128>>>(spikes, trials, ids, mask, expf_, out);
}